// round 16
// baseline (speedup 1.0000x reference)
#include <cuda_runtime.h>
#include <cstdint>

// ---------------------------------------------------------------------------
// EfficientAttention_Mapping: B=256, 2N=4096 (two halves of N=2048), D=3, DK=64
//
// Exact reformulation accumulated per (b,half):
//   qbar[j] = sum_n exp(lq[n,j]) / sum_j' exp(lq[n,j'])
//   kden[j] = sum_n exp(lk[n,j])
//   M[j][e] = sum_n exp(lk[n,j]) * x[n,e]     (e = 0..2)
// then
//   knum[j][d] = sum_e M[j][e]*Wv[e,d] + bv[d]*kden[j]
//   out_half[d] = (1/N) * sum_j qbar[j] * knum[j][d] / kden[j]
//
// Round 15: PERSISTENT grid (592 CTAs = 148 SMs x 4) looping over the same
// 4096 role-split work units as round 12. One wave instead of ~7: removes
// wave-transition overhead and per-CTA cold-start; weights staged once per
// CTA (role is fixed since 592 % 8 == 0). Unit math/layout identical to the
// best-measured variant (R11/12 split, 62 regs).
// ---------------------------------------------------------------------------

typedef unsigned long long ull;

__device__ __forceinline__ ull pack2(float lo, float hi) {
    ull r; asm("mov.b64 %0, {%1, %2};" : "=l"(r) : "f"(lo), "f"(hi)); return r;
}
__device__ __forceinline__ void unpack2(ull v, float& lo, float& hi) {
    asm("mov.b64 {%0, %1}, %2;" : "=f"(lo), "=f"(hi) : "l"(v));
}
__device__ __forceinline__ ull fma2(ull a, ull b, ull c) {
    ull d; asm("fma.rn.f32x2 %0, %1, %2, %3;" : "=l"(d) : "l"(a), "l"(b), "l"(c)); return d;
}
__device__ __forceinline__ ull add2(ull a, ull b) {
    ull d; asm("add.rn.f32x2 %0, %1, %2;" : "=l"(d) : "l"(a), "l"(b)); return d;
}
__device__ __forceinline__ float ex2f(float x) {
    float y; asm("ex2.approx.ftz.f32 %0, %1;" : "=f"(y) : "f"(x)); return y;
}
__device__ __forceinline__ float rcpf(float x) {
    float y; asm("rcp.approx.ftz.f32 %0, %1;" : "=f"(y) : "f"(x)); return y;
}
__device__ __forceinline__ ull ex2pair(ull v) {
    float a, b; unpack2(v, a, b);
    return pack2(ex2f(a), ex2f(b));
}

#define LOG2E_F 1.4426950408889634f
#define NCTAS   592
#define NUNITS  4096

// Scratch: 2048 row-blocks x 320 partials (qbar[64], M0[64], M1[64], M2[64], kden[64])
__device__ float g_part[2048 * 320];
__device__ int   g_cnt[256];   // zero-init; counts 16 arrivals/batch; reset each replay

__global__ __launch_bounds__(256, 4)
void ea_persist_kernel(const float* __restrict__ xin,
                       const float* __restrict__ Wq, const float* __restrict__ bq,
                       const float* __restrict__ Wk, const float* __restrict__ bk,
                       const float* __restrict__ Wv, const float* __restrict__ bv,
                       float* __restrict__ out)
{
    __shared__ ull         xs2[512 * 3];       // 12 KB: x chunk, value duplicated per pair
    __shared__ ulonglong2  wsu[2][2][16];      // 1 KB: this role's weight pairs (log2e-scaled)
    __shared__ float       red[5][8][64];      // 10 KB
    __shared__ int         s_old;
    __shared__ float       fsh[2][3];
    __shared__ float       ohalf[2][3];

    const int tid = threadIdx.x;
    const int blk = blockIdx.x;                // 0..591

    // Role is unit-invariant: unit = blk + 592*k and 592 % 8 == 0.
    const int  w3  = blk & 7;
    const bool isq = w3 < 4;

    // --- stage this role's weights ONCE: wsu[sp][u][c]: pair (j0=c+32u, j1=j0+16)
    {
        const float* W  = isq ? Wq : Wk;
        const float* bb = isq ? bq : bk;
        float4* wf = reinterpret_cast<float4*>(&wsu[0][0][0]);
        if (tid < 64) {
            int c  = tid & 15;
            int u  = (tid >> 4) & 1;
            int sp = tid >> 5;
            int j0 = c + 32 * u, j1 = j0 + 16;
            float a, b, cc, d;
            if (sp == 0) { a = W[j0];       b = W[j1];       cc = W[64 + j0]; d = W[64 + j1]; }
            else         { a = W[128 + j0]; b = W[128 + j1]; cc = bb[j0];     d = bb[j1]; }
            wf[tid] = make_float4(a * LOG2E_F, b * LOG2E_F, cc * LOG2E_F, d * LOG2E_F);
        }
    }
    __syncthreads();

    const int c    = tid & 15;     // j-slice index within group (0..15)
    const int g    = tid >> 4;     // group = row lane (16 groups, 32 rows each)
    const int lane = tid & 31;
    const int w    = tid >> 5;

    // hoisted weights for THIS role only: 4 ulonglong2 = 16 regs
    const ulonglong2 w01_0 = wsu[0][0][c], w2b_0 = wsu[1][0][c];
    const ulonglong2 w01_1 = wsu[0][1][c], w2b_1 = wsu[1][1][c];

    const ull Z = pack2(0.0f, 0.0f);

    // ================= persistent unit loop =================
    #pragma unroll 1
    for (int unit = blk; unit < NUNITS; unit += NCTAS) {
        const int rb = (unit >> 3) * 4 + (w3 & 3);  // row-block 0..2047

        // --- stage x chunk as duplicated pairs (1536 scalars, coalesced) ---
        {
            const float* src = xin + (size_t)rb * 1536;
            #pragma unroll
            for (int i = tid; i < 1536; i += 256) {
                const float v = src[i];
                xs2[i] = pack2(v, v);
            }
        }
        __syncthreads();

        if (isq) {
            // =================== q role: qbar only ===================
            ull qb2[2] = {Z, Z};

            #pragma unroll 1
            for (int it = 0; it < 16; ++it) {
                const int rA = g + (it << 5);
                const int rB = rA + 16;
                const ull XA0 = xs2[rA * 3 + 0], XA1 = xs2[rA * 3 + 1], XA2 = xs2[rA * 3 + 2];
                const ull XB0 = xs2[rB * 3 + 0], XB1 = xs2[rB * 3 + 1], XB2 = xs2[rB * 3 + 2];

                ull lq0A = fma2(XA0, w01_0.x, fma2(XA1, w01_0.y, fma2(XA2, w2b_0.x, w2b_0.y)));
                ull lq1A = fma2(XA0, w01_1.x, fma2(XA1, w01_1.y, fma2(XA2, w2b_1.x, w2b_1.y)));
                ull lq0B = fma2(XB0, w01_0.x, fma2(XB1, w01_0.y, fma2(XB2, w2b_0.x, w2b_0.y)));
                ull lq1B = fma2(XB0, w01_1.x, fma2(XB1, w01_1.y, fma2(XB2, w2b_1.x, w2b_1.y)));

                const ull eq0A = ex2pair(lq0A);
                const ull eq1A = ex2pair(lq1A);
                const ull eq0B = ex2pair(lq0B);
                const ull eq1B = ex2pair(lq1B);

                // packed dual-row butterfly over the 16-thread group
                ull tA = add2(eq0A, eq1A);
                ull tB = add2(eq0B, eq1B);
                float al, ah, bl, bh;
                unpack2(tA, al, ah);
                unpack2(tB, bl, bh);
                ull s2 = pack2(al + ah, bl + bh);
                s2 = add2(s2, __shfl_xor_sync(0xffffffffu, s2, 1));
                s2 = add2(s2, __shfl_xor_sync(0xffffffffu, s2, 2));
                s2 = add2(s2, __shfl_xor_sync(0xffffffffu, s2, 4));
                s2 = add2(s2, __shfl_xor_sync(0xffffffffu, s2, 8));
                float sA, sB;
                unpack2(s2, sA, sB);
                const float rAinv = rcpf(sA);
                const float rBinv = rcpf(sB);
                const ull RA = pack2(rAinv, rAinv);
                const ull RB = pack2(rBinv, rBinv);

                qb2[0] = fma2(eq0A, RA, qb2[0]);
                qb2[1] = fma2(eq1A, RA, qb2[1]);
                qb2[0] = fma2(eq0B, RB, qb2[0]);
                qb2[1] = fma2(eq1B, RB, qb2[1]);
            }

            // combine the 2 groups within each warp (bit 4)
            #pragma unroll
            for (int u = 0; u < 2; ++u)
                qb2[u] = add2(qb2[u], __shfl_xor_sync(0xffffffffu, qb2[u], 16));

            if (lane < 16) {
                #pragma unroll
                for (int u = 0; u < 2; ++u) {
                    const int j0 = lane + 32 * u, j1 = j0 + 16;
                    float a, b;
                    unpack2(qb2[u], a, b);
                    red[0][w][j0] = a; red[0][w][j1] = b;
                }
            }
            __syncthreads();

            if (tid < 64) {
                float s = 0.0f;
                #pragma unroll
                for (int ww = 0; ww < 8; ++ww) s += red[0][ww][tid];
                g_part[(size_t)rb * 320 + tid] = s;
            }
        } else {
            // =================== k role: M, kden (no shfl in loop) ===================
            ull M0[2] = {Z, Z}, M1[2] = {Z, Z}, M2a[2] = {Z, Z}, kd2[2] = {Z, Z};

            #pragma unroll 1
            for (int it = 0; it < 16; ++it) {
                const int rA = g + (it << 5);
                const int rB = rA + 16;
                const ull XA0 = xs2[rA * 3 + 0], XA1 = xs2[rA * 3 + 1], XA2 = xs2[rA * 3 + 2];
                const ull XB0 = xs2[rB * 3 + 0], XB1 = xs2[rB * 3 + 1], XB2 = xs2[rB * 3 + 2];

                ull lk0A = fma2(XA0, w01_0.x, fma2(XA1, w01_0.y, fma2(XA2, w2b_0.x, w2b_0.y)));
                ull lk1A = fma2(XA0, w01_1.x, fma2(XA1, w01_1.y, fma2(XA2, w2b_1.x, w2b_1.y)));
                ull lk0B = fma2(XB0, w01_0.x, fma2(XB1, w01_0.y, fma2(XB2, w2b_0.x, w2b_0.y)));
                ull lk1B = fma2(XB0, w01_1.x, fma2(XB1, w01_1.y, fma2(XB2, w2b_1.x, w2b_1.y)));

                ull ek = ex2pair(lk0A);
                kd2[0] = add2(kd2[0], ek);
                M0[0]  = fma2(ek, XA0, M0[0]);
                M1[0]  = fma2(ek, XA1, M1[0]);
                M2a[0] = fma2(ek, XA2, M2a[0]);

                ek = ex2pair(lk1A);
                kd2[1] = add2(kd2[1], ek);
                M0[1]  = fma2(ek, XA0, M0[1]);
                M1[1]  = fma2(ek, XA1, M1[1]);
                M2a[1] = fma2(ek, XA2, M2a[1]);

                ek = ex2pair(lk0B);
                kd2[0] = add2(kd2[0], ek);
                M0[0]  = fma2(ek, XB0, M0[0]);
                M1[0]  = fma2(ek, XB1, M1[0]);
                M2a[0] = fma2(ek, XB2, M2a[0]);

                ek = ex2pair(lk1B);
                kd2[1] = add2(kd2[1], ek);
                M0[1]  = fma2(ek, XB0, M0[1]);
                M1[1]  = fma2(ek, XB1, M1[1]);
                M2a[1] = fma2(ek, XB2, M2a[1]);
            }

            #pragma unroll
            for (int u = 0; u < 2; ++u) {
                M0[u]  = add2(M0[u],  __shfl_xor_sync(0xffffffffu, M0[u],  16));
                M1[u]  = add2(M1[u],  __shfl_xor_sync(0xffffffffu, M1[u],  16));
                M2a[u] = add2(M2a[u], __shfl_xor_sync(0xffffffffu, M2a[u], 16));
                kd2[u] = add2(kd2[u], __shfl_xor_sync(0xffffffffu, kd2[u], 16));
            }

            if (lane < 16) {
                #pragma unroll
                for (int u = 0; u < 2; ++u) {
                    const int j0 = lane + 32 * u, j1 = j0 + 16;
                    float a, b;
                    unpack2(M0[u],  a, b); red[1][w][j0] = a; red[1][w][j1] = b;
                    unpack2(M1[u],  a, b); red[2][w][j0] = a; red[2][w][j1] = b;
                    unpack2(M2a[u], a, b); red[3][w][j0] = a; red[3][w][j1] = b;
                    unpack2(kd2[u], a, b); red[4][w][j0] = a; red[4][w][j1] = b;
                }
            }
            __syncthreads();

            // write the 256 k-side partials (slots 64..320)
            {
                const int vi  = 64 + tid;          // 64..319
                const int acc = vi >> 6, j = vi & 63;
                float s = 0.0f;
                #pragma unroll
                for (int ww = 0; ww < 8; ++ww) s += red[acc][ww][j];
                g_part[(size_t)rb * 320 + vi] = s;
            }
        }

        // ------------- fused finalize: last of 16 arrivals per batch -------------
        const int bb = rb >> 3;
        __syncthreads();                    // all g_part stores of this unit done
        if (tid == 0) {
            __threadfence();                // publish g_part before counter bump
            s_old = atomicAdd(&g_cnt[bb], 1);
        }
        __syncthreads();
        if (s_old != 15) continue;          // not the last arrival -> next unit

        __threadfence();                    // acquire: see all 16 contributions

        const int j = tid;
        if (j < 64) {
            for (int h = 0; h < 2; ++h) {
                float qb = 0.0f, m0 = 0.0f, m1 = 0.0f, m2 = 0.0f, kd = 0.0f;
                const size_t base = (size_t)(bb * 8 + h * 4) * 320;
                #pragma unroll
                for (int s = 0; s < 4; ++s) {
                    const float* p = g_part + base + (size_t)s * 320;
                    qb += p[j];
                    m0 += p[64 + j];
                    m1 += p[128 + j];
                    m2 += p[192 + j];
                    kd += p[256 + j];
                }
                const float rkd = 1.0f / kd;
                float t[3];
                #pragma unroll
                for (int d = 0; d < 3; ++d) {
                    const float kn = m0 * Wv[0 * 3 + d] + m1 * Wv[1 * 3 + d]
                                   + m2 * Wv[2 * 3 + d] + bv[d] * kd;
                    t[d] = qb * (kn * rkd);
                }
                #pragma unroll
                for (int o = 16; o >= 1; o >>= 1) {
                    t[0] += __shfl_xor_sync(0xffffffffu, t[0], o);
                    t[1] += __shfl_xor_sync(0xffffffffu, t[1], o);
                    t[2] += __shfl_xor_sync(0xffffffffu, t[2], o);
                }
                const int ww = j >> 5;
                if ((j & 31) == 0) { fsh[ww][0] = t[0]; fsh[ww][1] = t[1]; fsh[ww][2] = t[2]; }
                __syncwarp(0xffffffffu);
                if (h == 0) {
                    __syncthreads();
                    if (j == 0)
                        for (int d = 0; d < 3; ++d)
                            ohalf[0][d] = (fsh[0][d] + fsh[1][d]) * (1.0f / 2048.0f);
                    __syncthreads();
                }
            }
        } else {
            __syncthreads();
            __syncthreads();
        }
        __syncthreads();
        if (j == 0) {
            const float oh1_0 = (fsh[0][0] + fsh[1][0]) * (1.0f / 2048.0f);
            const float oh1_1 = (fsh[0][1] + fsh[1][1]) * (1.0f / 2048.0f);
            const float oh1_2 = (fsh[0][2] + fsh[1][2]) * (1.0f / 2048.0f);
            const float a0 = 0.5f * (ohalf[0][0] + oh1_0);
            const float a1 = 0.5f * (ohalf[0][1] + oh1_1);
            const float a2 = 0.5f * (ohalf[0][2] + oh1_2);
            const float inv = rsqrtf(a0 * a0 + a1 * a1 + a2 * a2);
            out[bb * 3 + 0] = a0 * inv;
            out[bb * 3 + 1] = a1 * inv;
            out[bb * 3 + 2] = a2 * inv;
            g_cnt[bb] = 0;                  // reset for next graph replay
        }
        __syncthreads();                    // finalize reads done before next unit
    }
}

// ---------------------------------------------------------------------------
extern "C" void kernel_launch(void* const* d_in, const int* in_sizes, int n_in,
                              void* d_out, int out_size)
{
    const float* xin = (const float*)d_in[0];
    const float* Wq  = (const float*)d_in[1];
    const float* bq  = (const float*)d_in[2];
    const float* Wk  = (const float*)d_in[3];
    const float* bk  = (const float*)d_in[4];
    const float* Wv  = (const float*)d_in[5];
    const float* bv  = (const float*)d_in[6];
    float* out = (float*)d_out;

    ea_persist_kernel<<<NCTAS, 256>>>(xin, Wq, bq, Wk, bk, Wv, bv, out);
}

// round 17
// speedup vs baseline: 1.4278x; 1.4278x over previous
#include <cuda_runtime.h>
#include <cstdint>

// ---------------------------------------------------------------------------
// EfficientAttention_Mapping: B=256, 2N=4096 (two halves of N=2048), D=3, DK=64
//
// Exact reformulation accumulated per (b,half):
//   qbar[j] = sum_n exp(lq[n,j]) / sum_j' exp(lq[n,j'])
//   kden[j] = sum_n exp(lk[n,j])     [bk dropped: exp(bk_j) scales kden[j] and
//                                     M[j] identically and cancels in knum/kden]
//   M[j][e] = sum_n exp(lk[n,j]) * x[n,e]
// then
//   knum[j][d] = sum_e M[j][e]*Wv[e,d] + bv[d]*kden[j]
//   out_half[d] = (1/N) * sum_j qbar[j] * knum[j][d] / kden[j]
//
// Round 16 = best-measured base (R6/R7 combined kernel, 51.26us) plus:
//   (1) rotating XA prefetch: next iteration's XA is loaded mid-iteration so
//       the only hard-exposed LDS (XA consumed at iteration top) is hidden;
//   (2) bk dropped (exact), freeing the two bias register-pairs to pay for
//       the prefetch registers under the 84-reg / 3-CTA cap.
// ---------------------------------------------------------------------------

typedef unsigned long long ull;

__device__ __forceinline__ ull pack2(float lo, float hi) {
    ull r; asm("mov.b64 %0, {%1, %2};" : "=l"(r) : "f"(lo), "f"(hi)); return r;
}
__device__ __forceinline__ void unpack2(ull v, float& lo, float& hi) {
    asm("mov.b64 {%0, %1}, %2;" : "=f"(lo), "=f"(hi) : "l"(v));
}
__device__ __forceinline__ ull fma2(ull a, ull b, ull c) {
    ull d; asm("fma.rn.f32x2 %0, %1, %2, %3;" : "=l"(d) : "l"(a), "l"(b), "l"(c)); return d;
}
__device__ __forceinline__ ull add2(ull a, ull b) {
    ull d; asm("add.rn.f32x2 %0, %1, %2;" : "=l"(d) : "l"(a), "l"(b)); return d;
}
__device__ __forceinline__ ull mul2(ull a, ull b) {
    ull d; asm("mul.rn.f32x2 %0, %1, %2;" : "=l"(d) : "l"(a), "l"(b)); return d;
}
__device__ __forceinline__ float ex2f(float x) {
    float y; asm("ex2.approx.ftz.f32 %0, %1;" : "=f"(y) : "f"(x)); return y;
}
__device__ __forceinline__ float rcpf(float x) {
    float y; asm("rcp.approx.ftz.f32 %0, %1;" : "=f"(y) : "f"(x)); return y;
}
__device__ __forceinline__ ull ex2pair(ull v) {
    float a, b; unpack2(v, a, b);
    return pack2(ex2f(a), ex2f(b));
}

#define LOG2E_F 1.4426950408889634f

// Scratch: 2048 row-blocks x 320 partials (qbar[64], M0[64], M1[64], M2[64], kden[64])
__device__ float g_part[2048 * 320];
__device__ int   g_cnt[256];   // zero-init; reset by finalizer each replay

__global__ __launch_bounds__(256, 3)
void ea_fused_kernel(const float* __restrict__ xin,
                     const float* __restrict__ Wq, const float* __restrict__ bq,
                     const float* __restrict__ Wk, const float* __restrict__ bk,
                     const float* __restrict__ Wv, const float* __restrict__ bv,
                     float* __restrict__ out)
{
    __shared__ ull         xs2[512 * 3];       // 12 KB: x chunk, value duplicated per pair
    __shared__ ulonglong2  wsu[4][2][16];      // 2 KB: weight pairs, pre-scaled by log2e
    __shared__ float       red[5][8][64];      // 10 KB: end-of-CTA reduction
    __shared__ int         s_old;
    __shared__ float       fsh[2][3];
    __shared__ float       ohalf[2][3];

    const int tid = threadIdx.x;
    const int blk = blockIdx.x;                // 0..2047; batch = blk>>3

    // --- stage x chunk as duplicated pairs (1536 scalars, coalesced) ---
    {
        const float* src = xin + (size_t)blk * 1536;
        #pragma unroll
        for (int i = tid; i < 1536; i += 256) {
            const float v = src[i];
            xs2[i] = pack2(v, v);
        }
    }

    // --- stage weights: wsu[sp][u][c]: pair (j0=c+32u, j1=j0+16)
    // sp0: (Wq row0 pair, Wq row1 pair)   sp1: (Wq row2 pair, bq pair)
    // sp2: (Wk row0 pair, Wk row1 pair)   sp3: (Wk row2 pair, ZERO — bk cancels)
    {
        float4* wf = reinterpret_cast<float4*>(&wsu[0][0][0]);
        for (int i = tid; i < 128; i += 256) {
            int c  = i & 15;
            int u  = (i >> 4) & 1;
            int sp = i >> 5;
            int j0 = c + 32 * u, j1 = j0 + 16;
            float a, b, cc, d;
            if (sp == 0)      { a = Wq[j0];       b = Wq[j1];       cc = Wq[64 + j0];  d = Wq[64 + j1]; }
            else if (sp == 1) { a = Wq[128 + j0]; b = Wq[128 + j1]; cc = bq[j0];       d = bq[j1]; }
            else if (sp == 2) { a = Wk[j0];       b = Wk[j1];       cc = Wk[64 + j0];  d = Wk[64 + j1]; }
            else              { a = Wk[128 + j0]; b = Wk[128 + j1]; cc = 0.0f;         d = 0.0f; }
            wf[i] = make_float4(a * LOG2E_F, b * LOG2E_F, cc * LOG2E_F, d * LOG2E_F);
        }
    }
    __syncthreads();

    const int c = tid & 15;       // j-slice index within group (0..15)
    const int g = tid >> 4;       // group = row lane (16 groups)

    // hoisted weights: q 4 ulonglong2 (16 regs) + k 2 ulonglong2 + 2 ull (12 regs)
    const ulonglong2 wq01_0 = wsu[0][0][c], wq2b_0 = wsu[1][0][c];
    const ulonglong2 wq01_1 = wsu[0][1][c], wq2b_1 = wsu[1][1][c];
    const ulonglong2 wk01_0 = wsu[2][0][c];
    const ulonglong2 wk01_1 = wsu[2][1][c];
    const ull        w2k_0  = wsu[3][0][c].x;
    const ull        w2k_1  = wsu[3][1][c].x;

    const ull Z = pack2(0.0f, 0.0f);
    ull qb2[2], M0[2], M1[2], M2a[2], kd2[2];
    #pragma unroll
    for (int u = 0; u < 2; ++u) { qb2[u] = Z; M0[u] = Z; M1[u] = Z; M2a[u] = Z; kd2[u] = Z; }

    // rotating prefetch of row A (row A is consumed at iteration top; B has
    // natural overlap under A's compute)
    ull XA0 = xs2[g * 3 + 0], XA1 = xs2[g * 3 + 1], XA2 = xs2[g * 3 + 2];

    #pragma unroll 1
    for (int it = 0; it < 16; ++it) {
        const int rB  = g + (it << 5) + 16;
        const int rAn = g + (((it + 1) & 15) << 5);   // next iter's row A (wrap harmless)
        const ull XB0 = xs2[rB * 3 + 0], XB1 = xs2[rB * 3 + 1], XB2 = xs2[rB * 3 + 2];

        // ---- row A (uses prefetched XA) ----
        ull lq0 = fma2(XA0, wq01_0.x, fma2(XA1, wq01_0.y, fma2(XA2, wq2b_0.x, wq2b_0.y)));
        ull lq1 = fma2(XA0, wq01_1.x, fma2(XA1, wq01_1.y, fma2(XA2, wq2b_1.x, wq2b_1.y)));
        ull lk0 = fma2(XA0, wk01_0.x, fma2(XA1, wk01_0.y, mul2(XA2, w2k_0)));
        ull lk1 = fma2(XA0, wk01_1.x, fma2(XA1, wk01_1.y, mul2(XA2, w2k_1)));

        const ull eq0A = ex2pair(lq0);
        const ull eq1A = ex2pair(lq1);
        ull ek = ex2pair(lk0);
        kd2[0] = add2(kd2[0], ek);
        M0[0]  = fma2(ek, XA0, M0[0]);
        M1[0]  = fma2(ek, XA1, M1[0]);
        M2a[0] = fma2(ek, XA2, M2a[0]);
        ek = ex2pair(lk1);
        kd2[1] = add2(kd2[1], ek);
        M0[1]  = fma2(ek, XA0, M0[1]);
        M1[1]  = fma2(ek, XA1, M1[1]);
        M2a[1] = fma2(ek, XA2, M2a[1]);

        // ---- prefetch next iteration's row A (XA now dead) ----
        XA0 = xs2[rAn * 3 + 0];
        XA1 = xs2[rAn * 3 + 1];
        XA2 = xs2[rAn * 3 + 2];

        // ---- row B ----
        lq0 = fma2(XB0, wq01_0.x, fma2(XB1, wq01_0.y, fma2(XB2, wq2b_0.x, wq2b_0.y)));
        lq1 = fma2(XB0, wq01_1.x, fma2(XB1, wq01_1.y, fma2(XB2, wq2b_1.x, wq2b_1.y)));
        lk0 = fma2(XB0, wk01_0.x, fma2(XB1, wk01_0.y, mul2(XB2, w2k_0)));
        lk1 = fma2(XB0, wk01_1.x, fma2(XB1, wk01_1.y, mul2(XB2, w2k_1)));

        const ull eq0B = ex2pair(lq0);
        const ull eq1B = ex2pair(lq1);
        ek = ex2pair(lk0);
        kd2[0] = add2(kd2[0], ek);
        M0[0]  = fma2(ek, XB0, M0[0]);
        M1[0]  = fma2(ek, XB1, M1[0]);
        M2a[0] = fma2(ek, XB2, M2a[0]);
        ek = ex2pair(lk1);
        kd2[1] = add2(kd2[1], ek);
        M0[1]  = fma2(ek, XB0, M0[1]);
        M1[1]  = fma2(ek, XB1, M1[1]);
        M2a[1] = fma2(ek, XB2, M2a[1]);

        // ---- packed dual-row softmax-denominator butterfly ----
        ull tA = add2(eq0A, eq1A);
        ull tB = add2(eq0B, eq1B);
        float al, ah, bl, bh;
        unpack2(tA, al, ah);
        unpack2(tB, bl, bh);
        ull s2 = pack2(al + ah, bl + bh);      // (sumA, sumB) in one 64-bit value
        s2 = add2(s2, __shfl_xor_sync(0xffffffffu, s2, 1));
        s2 = add2(s2, __shfl_xor_sync(0xffffffffu, s2, 2));
        s2 = add2(s2, __shfl_xor_sync(0xffffffffu, s2, 4));
        s2 = add2(s2, __shfl_xor_sync(0xffffffffu, s2, 8));
        float sA, sB;
        unpack2(s2, sA, sB);
        const float rAinv = rcpf(sA);
        const float rBinv = rcpf(sB);
        const ull RA = pack2(rAinv, rAinv);
        const ull RB = pack2(rBinv, rBinv);

        qb2[0] = fma2(eq0A, RA, qb2[0]);
        qb2[1] = fma2(eq1A, RA, qb2[1]);
        qb2[0] = fma2(eq0B, RB, qb2[0]);
        qb2[1] = fma2(eq1B, RB, qb2[1]);
    }

    // --- combine the 2 groups within each warp (lanes differ in bit 4) ---
    #pragma unroll
    for (int u = 0; u < 2; ++u) {
        qb2[u] = add2(qb2[u], __shfl_xor_sync(0xffffffffu, qb2[u], 16));
        M0[u]  = add2(M0[u],  __shfl_xor_sync(0xffffffffu, M0[u],  16));
        M1[u]  = add2(M1[u],  __shfl_xor_sync(0xffffffffu, M1[u],  16));
        M2a[u] = add2(M2a[u], __shfl_xor_sync(0xffffffffu, M2a[u], 16));
        kd2[u] = add2(kd2[u], __shfl_xor_sync(0xffffffffu, kd2[u], 16));
    }

    const int lane = tid & 31;
    const int w    = tid >> 5;
    if (lane < 16) {
        #pragma unroll
        for (int u = 0; u < 2; ++u) {
            const int j0 = lane + 32 * u, j1 = j0 + 16;
            float a, b;
            unpack2(qb2[u], a, b); red[0][w][j0] = a; red[0][w][j1] = b;
            unpack2(M0[u],  a, b); red[1][w][j0] = a; red[1][w][j1] = b;
            unpack2(M1[u],  a, b); red[2][w][j0] = a; red[2][w][j1] = b;
            unpack2(M2a[u], a, b); red[3][w][j0] = a; red[3][w][j1] = b;
            unpack2(kd2[u], a, b); red[4][w][j0] = a; red[4][w][j1] = b;
        }
    }
    __syncthreads();

    for (int vi = tid; vi < 320; vi += 256) {
        const int acc = vi >> 6, j = vi & 63;
        float s = 0.0f;
        #pragma unroll
        for (int ww = 0; ww < 8; ++ww) s += red[acc][ww][j];
        g_part[(size_t)blk * 320 + vi] = s;
    }

    // ---------------- fused finalize: last CTA per batch ----------------
    const int bb = blk >> 3;
    __syncthreads();                    // all g_part stores of this CTA done
    if (tid == 0) {
        __threadfence();                // publish g_part before counter bump
        s_old = atomicAdd(&g_cnt[bb], 1);
    }
    __syncthreads();
    if (s_old != 7) return;

    __threadfence();                    // acquire: see all 8 blocks' g_part

    const int j = tid;
    if (j < 64) {
        for (int h = 0; h < 2; ++h) {
            float qb = 0.0f, m0 = 0.0f, m1 = 0.0f, m2 = 0.0f, kd = 0.0f;
            const size_t base = (size_t)(bb * 8 + h * 4) * 320;
            #pragma unroll
            for (int s = 0; s < 4; ++s) {
                const float* p = g_part + base + (size_t)s * 320;
                qb += p[j];
                m0 += p[64 + j];
                m1 += p[128 + j];
                m2 += p[192 + j];
                kd += p[256 + j];
            }
            const float rkd = 1.0f / kd;
            float t[3];
            #pragma unroll
            for (int d = 0; d < 3; ++d) {
                const float kn = m0 * Wv[0 * 3 + d] + m1 * Wv[1 * 3 + d]
                               + m2 * Wv[2 * 3 + d] + bv[d] * kd;
                t[d] = qb * (kn * rkd);
            }
            #pragma unroll
            for (int o = 16; o >= 1; o >>= 1) {
                t[0] += __shfl_xor_sync(0xffffffffu, t[0], o);
                t[1] += __shfl_xor_sync(0xffffffffu, t[1], o);
                t[2] += __shfl_xor_sync(0xffffffffu, t[2], o);
            }
            const int ww = j >> 5;
            if ((j & 31) == 0) { fsh[ww][0] = t[0]; fsh[ww][1] = t[1]; fsh[ww][2] = t[2]; }
            __syncwarp(0xffffffffu);
            if (h == 0) {
                __syncthreads();
                if (j == 0)
                    for (int d = 0; d < 3; ++d)
                        ohalf[0][d] = (fsh[0][d] + fsh[1][d]) * (1.0f / 2048.0f);
                __syncthreads();
            }
        }
    } else {
        __syncthreads();
        __syncthreads();
    }
    __syncthreads();
    if (j == 0) {
        const float oh1_0 = (fsh[0][0] + fsh[1][0]) * (1.0f / 2048.0f);
        const float oh1_1 = (fsh[0][1] + fsh[1][1]) * (1.0f / 2048.0f);
        const float oh1_2 = (fsh[0][2] + fsh[1][2]) * (1.0f / 2048.0f);
        const float a0 = 0.5f * (ohalf[0][0] + oh1_0);
        const float a1 = 0.5f * (ohalf[0][1] + oh1_1);
        const float a2 = 0.5f * (ohalf[0][2] + oh1_2);
        const float inv = rsqrtf(a0 * a0 + a1 * a1 + a2 * a2);
        out[bb * 3 + 0] = a0 * inv;
        out[bb * 3 + 1] = a1 * inv;
        out[bb * 3 + 2] = a2 * inv;
        g_cnt[bb] = 0;                  // reset for next graph replay
    }
}

// ---------------------------------------------------------------------------
extern "C" void kernel_launch(void* const* d_in, const int* in_sizes, int n_in,
                              void* d_out, int out_size)
{
    const float* xin = (const float*)d_in[0];
    const float* Wq  = (const float*)d_in[1];
    const float* bq  = (const float*)d_in[2];
    const float* Wk  = (const float*)d_in[3];
    const float* bk  = (const float*)d_in[4];
    const float* Wv  = (const float*)d_in[5];
    const float* bv  = (const float*)d_in[6];
    float* out = (float*)d_out;

    ea_fused_kernel<<<2048, 256>>>(xin, Wq, bq, Wk, bk, Wv, bv, out);
}